// round 10
// baseline (speedup 1.0000x reference)
#include <cuda_runtime.h>
#include <math.h>

#define NMAX 32
#define BMAX 8
#define LEVELS 6

// SIZES computed in double then rounded to f32, matching numpy/jax promotion.
__constant__ float c_UPPER[LEVELS] = {
    (float)(2.23147392 * 22050.0 / 256.0),
    (float)(2.62519274 * 22050.0 / 256.0),
    (float)(3.74199546 * 22050.0 / 256.0),
    (float)(5.78800454 * 22050.0 / 256.0),
    (float)(8.02371882 * 22050.0 / 256.0),
    INFINITY
};
__constant__ float c_LOWER[LEVELS] = {
    0.0f,
    (float)(2.23147392 * 22050.0 / 256.0),
    (float)(2.62519274 * 22050.0 / 256.0),
    (float)(3.74199546 * 22050.0 / 256.0),
    (float)(5.78800454 * 22050.0 / 256.0),
    (float)(8.02371882 * 22050.0 / 256.0)
};

// Persistent accumulators. Zero-initialized at module load; the last block of
// every launch resets them, so each launch/replay starts clean.
__device__ float    g_loss[BMAX];
__device__ float    g_cnt[BMAX];
__device__ unsigned g_counter;

__device__ __forceinline__ float ld_l2(const float* p) {
    float v;
    asm volatile("ld.global.cg.f32 %0, [%1];" : "=f"(v) : "l"(p));
    return v;
}

// ---------------------------------------------------------------------------
// One block per (sample b, ORIGINAL annotation index j); all 6 levels fused.
// The reference's winner for an anchor = the cand annotation minimizing
// (length, original index) lexicographically. Block (b,j) contributes anchor a
// at level i iff cand(j,a,i) AND no k with (len_k,k) <lex (len_j,j) has
// cand(k,a,i). All cand tests are bit-identical to the reference arithmetic.
//
// Warp 0 precomputes per level:
//   - conservative candidate anchor-index interval for j (lo/width/prefix)
//   - a 32-bit "possible blocker" mask: k is kept only if it is lex-smaller
//     AND its length is compatible with the level band (conservative margins,
//     so no true blocker is ever dropped; survivors get the exact test).
// Threads then strip-mine the fused (level, anchor) index space.
// ---------------------------------------------------------------------------
__global__ void k_fused(const float* __restrict__ ann,
                        const float* __restrict__ reg,
                        float* __restrict__ out,
                        int B, int L0, int A) {
    const int bid = blockIdx.x;
    const int b   = bid / NMAX;
    const int j   = bid % NMAX;

    __shared__ float2   sh_se[NMAX];          // (start, end) per annotation
    __shared__ float    sh_len[NMAX];
    __shared__ unsigned sh_mask[LEVELS];      // possible blockers per level
    __shared__ int      sh_lo[LEVELS];        // interval start (anchor idx)
    __shared__ int      sh_w[LEVELS];         // interval width
    __shared__ int      sh_cum[LEVELS];       // prefix start in fused index
    __shared__ int      sh_off[LEVELS];       // pyramid row offset of level
    __shared__ int      sh_W;                 // total fused width

    const int t = threadIdx.x;

    if (t < NMAX) {
        float s = ann[(b * NMAX + t) * 3 + 0];
        float e = ann[(b * NMAX + t) * 3 + 1];
        sh_se[t]  = make_float2(s, e);
        sh_len[t] = e - s;
    }
    __syncthreads();

    const float2 sej  = sh_se[j];
    const float  sj   = sej.x, ej = sej.y;
    const float  lenj = sh_len[j];

    // --- warp 0: masks, intervals, prefix ---
    if (t < 32) {
        // blocker masks (all 32 lanes participate in each ballot)
        float lk = sh_len[t];
        bool smaller = (lk < lenj) || (lk == lenj && t < j);
        #pragma unroll
        for (int i = 0; i < LEVELS; i++) {
            // conservative length-band filter: cand(k,·,i) requires
            // m2 <= len_k (so len_k >= lower up to an ulp) and
            // m2 >= ~len_k/2 (so len_k < ~2*upper). Margins keep it safe.
            bool poss = smaller && (lk >= c_LOWER[i] - 1.0f)
                                && (lk * 0.498f < c_UPPER[i]);
            unsigned m = __ballot_sync(0xFFFFFFFFu, poss);
            if (t == 0) sh_mask[i] = m;
        }

        // per-level conservative interval for j (lanes 0..5)
        if (t < LEVELS) {
            const int   i     = t;
            const float lower = c_LOWER[i];
            const float upper = c_UPPER[i];
            const float inv   = 1.0f / (float)(1 << i);
            int loi = 0, wi = 0;
            // m <= len (monotone fp rounding), so len < lower => never cand.
            if (lenj >= lower) {
                float lo_pt = fmaxf(sj, ej - upper);   // e - inf -> s
                float hi_pt = fminf(ej, sj + upper);   // s + inf -> e
                int lo = (int)floorf(lo_pt * inv - 0.5f) - 2;
                int hi = (int)ceilf (hi_pt * inv - 0.5f) + 2;
                int Li = L0 >> i;
                lo = lo < 0 ? 0 : lo;
                hi = hi > Li - 1 ? Li - 1 : hi;
                if (lo <= hi) { loi = lo; wi = hi - lo + 1; }
            }
            sh_lo[i] = loi;
            sh_w[i]  = wi;
            int off = 0;
            #pragma unroll
            for (int q = 0; q < LEVELS; q++) off += (q < i) ? (L0 >> q) : 0;
            sh_off[i] = off;
        }
        __syncwarp();
        if (t == 0) {
            int c = 0;
            #pragma unroll
            for (int i = 0; i < LEVELS; i++) { sh_cum[i] = c; c += sh_w[i]; }
            sh_W = c;
        }
    }
    __syncthreads();

    const int W = sh_W;
    float lsum = 0.0f, lcnt = 0.0f;

    for (int u = t; u < W; u += blockDim.x) {
        // decode fused index -> (level, anchor)
        int lev = 0;
        #pragma unroll
        for (int i = 1; i < LEVELS; i++) lev += (u >= sh_cum[i]);
        const int a = u - sh_cum[lev] + sh_lo[lev];

        const float scale = (float)(1 << lev);
        const float inv   = 1.0f / scale;
        const float lower = c_LOWER[lev];
        const float upper = c_UPPER[lev];

        const float pt = ((float)a + 0.5f) * scale;
        const float l  = pt - sj;
        const float r  = ej - pt;
        const float m  = fmaxf(l, r);
        bool cand = (l >= 0.0f) & (r >= 0.0f) & (m >= lower) & (m < upper);
        if (!cand) continue;

        // issue the regression load now; DRAM latency overlaps the scan
        const float2 rb =
            __ldcg(&((const float2*)reg)[(size_t)b * A + sh_off[lev] + a]);

        // winner iff no possible blocker is actually cand at this anchor
        bool first = true;
        unsigned msk = sh_mask[lev];
        while (msk) {
            const int k = __ffs(msk) - 1;
            msk &= msk - 1;
            const float2 se = sh_se[k];
            const float l2 = pt - se.x;
            const float r2 = se.y - pt;
            const float m2 = fmaxf(l2, r2);
            if ((l2 >= 0.0f) & (r2 >= 0.0f) & (m2 >= lower) & (m2 < upper)) {
                first = false;
                break;
            }
        }
        if (!first) continue;

        const float nl = l * inv;
        const float nr = r * inv;
        const float a0 = pt - nl;
        const float a1 = pt + nr;
        const float b0 = rb.x, b1 = rb.y;

        float inter = fminf(a1, b1) - fmaxf(a0, b0);
        inter = fmaxf(inter, 0.0f);
        const float uni  = (a1 - a0) + (b1 - b0) - inter;
        const float iou  = __fdividef(inter, uni + 1e-7f);
        const float enc  = fmaxf(a1, b1) - fminf(a0, b0);
        float giou = iou - __fdividef(enc - uni, enc + 1e-7f);
        giou = fminf(fmaxf(giou, -1.0f), 1.0f);

        lsum += 1.0f - giou;
        lcnt += 1.0f;
    }

    // --- warp reduction, sparse atomics ---
    #pragma unroll
    for (int o = 16; o > 0; o >>= 1) {
        lsum += __shfl_down_sync(0xFFFFFFFFu, lsum, o);
        lcnt += __shfl_down_sync(0xFFFFFFFFu, lcnt, o);
    }
    if ((t & 31) == 0 && lcnt > 0.0f) {
        atomicAdd(&g_loss[b], lsum);
        atomicAdd(&g_cnt[b], lcnt);
    }

    // --- last-block finalize; only warp 0 past the sync ---
    __threadfence();
    __syncthreads();            // all block atomics issued before counter bump
    if (t < 32) {
        unsigned v = 0;
        if (t == 0) v = atomicAdd(&g_counter, 1u);
        v = __shfl_sync(0xFFFFFFFFu, v, 0);
        if (v == gridDim.x - 1) {
            if (t < B) {
                // prior updates are L2 atomics + fence: read via L2 (ld.cg)
                float ls = ld_l2(&g_loss[t]);
                float cn = ld_l2(&g_cnt[t]);
                out[t] = __fdividef(ls, fmaxf(cn, 1.0f));
                g_loss[t] = 0.0f;
                g_cnt[t]  = 0.0f;
            }
            if (t == 0) g_counter = 0;
        }
    }
}

// ---------------------------------------------------------------------------
// Launch. Inputs identified by element count (robust to metadata ordering):
//   regressions = max size; class_id = 1; anchors = power-of-two sizes (>1);
//   annotations = the remaining input. B = ann_size / 96.
// ---------------------------------------------------------------------------
extern "C" void kernel_launch(void* const* d_in, const int* in_sizes, int n_in,
                              void* d_out, int out_size) {
    int reg_i = -1;
    long reg_sz = -1;
    for (int i = 0; i < n_in; i++) {
        if ((long)in_sizes[i] > reg_sz) { reg_sz = in_sizes[i]; reg_i = i; }
    }
    int ann_i = -1;
    int L0 = 0;
    for (int i = 0; i < n_in; i++) {
        if (i == reg_i) continue;
        int s = in_sizes[i];
        if (s <= 1) continue;                 // class_id
        bool pow2 = (s & (s - 1)) == 0;
        if (pow2) { if (s > L0) L0 = s; }     // anchors; L0 = largest level
        else       { ann_i = i; }             // annotations (B*32*3, not pow2)
    }

    int B = in_sizes[ann_i] / (NMAX * 3);
    if (B > BMAX) B = BMAX;
    int A = (int)(reg_sz / (2 * B));

    const float* reg = (const float*)d_in[reg_i];
    const float* ann = (const float*)d_in[ann_i];
    float* out = (float*)d_out;

    k_fused<<<B * NMAX, 128>>>(ann, reg, out, B, L0, A);
}